// round 3
// baseline (speedup 1.0000x reference)
#include <cuda_runtime.h>

// Problem constants
#define BB    16
#define CIN   128
#define COUT  128
#define HH    128
#define WW    128
#define KK    9        // 3x3 taps
#define SDIM  512

// Conv tiling
#define TH    4        // output rows per block
#define TW    32       // output cols per block
#define OCT   32       // output channels per block
#define CIT   16       // cin chunk staged in smem
#define ROWW  36       // smem input row pitch (34 used); mult of 4 -> aligned float4,
                       // and per-128-bit-phase (one pr row) covers all 32 banks conflict-free

// Scratch (allocation-free rule: __device__ globals)
__device__ float g_s[BB * CIN];                        // [b][i]
__device__ float g_wmod[(size_t)BB * CIN * KK * COUT]; // [b][i][t][o]

// ---- packed fp32x2 helpers (sm_100+ FFMA2 path; ptxas never auto-emits) ----
__device__ __forceinline__ unsigned long long pk2(float a, float b) {
    unsigned long long r;
    asm("mov.b64 %0, {%1, %2};" : "=l"(r) : "f"(a), "f"(b));
    return r;
}
__device__ __forceinline__ void ffma2(unsigned long long& d,
                                      unsigned long long a,
                                      unsigned long long b) {
    asm("fma.rn.f32x2 %0, %1, %2, %0;" : "+l"(d) : "l"(a), "l"(b));
}
__device__ __forceinline__ float2 upk2(unsigned long long v) {
    float2 f;
    asm("mov.b64 {%0, %1}, %2;" : "=f"(f.x), "=f"(f.y) : "l"(v));
    return f;
}

// ---------------------------------------------------------------------------
// Kernel 1: s[b][i] = lin_scale * (style[b] . mod_w[i]) + mod_b[i]
// Warp-per-output: 2048 warps total (was 2048 threads serial -> 40us latency).
// ---------------------------------------------------------------------------
__global__ void modulate_kernel(const float* __restrict__ style,
                                const float* __restrict__ mod_w,
                                const float* __restrict__ mod_b) {
    const int gw   = blockIdx.x * 8 + (threadIdx.x >> 5);  // global warp 0..2047
    const int lane = threadIdx.x & 31;
    const int b = gw >> 7;        // /CIN
    const int i = gw & 127;       // %CIN
    const float lin_scale = 0.044194173824159216f;  // 1/sqrt(512)
    const float* st = style + b * SDIM;
    const float* mw = mod_w + i * SDIM;
    float acc = 0.f;
#pragma unroll
    for (int d = 0; d < SDIM / 32; d++)
        acc += st[d * 32 + lane] * mw[d * 32 + lane];
#pragma unroll
    for (int off = 16; off > 0; off >>= 1)
        acc += __shfl_xor_sync(0xffffffffu, acc, off);
    if (lane == 0) g_s[b * CIN + i] = acc * lin_scale + mod_b[i];
}

// ---------------------------------------------------------------------------
// Kernel 2: per (b, o): demod = rsqrt(sum_{i,t} (scale*w*s)^2 + 1e-8)
//           write g_wmod[b][i][t][o] = scale * w[o][i][t] * s[b][i] * demod
// ---------------------------------------------------------------------------
__global__ void weight_kernel(const float* __restrict__ weight) {
    const int o = blockIdx.x;
    const int b = blockIdx.y;
    const int i = threadIdx.x;  // 128 threads
    const float scale = 0.029462782549439483f;  // 1/sqrt(1152)

    const float s = g_s[b * CIN + i];
    float wm[KK];
    float sq = 0.f;
#pragma unroll
    for (int t = 0; t < KK; t++) {
        float w = weight[(o * CIN + i) * KK + t] * scale * s;
        wm[t] = w;
        sq += w * w;
    }
    __shared__ float red[4];
#pragma unroll
    for (int off = 16; off > 0; off >>= 1)
        sq += __shfl_xor_sync(0xffffffffu, sq, off);
    if ((i & 31) == 0) red[i >> 5] = sq;
    __syncthreads();
    const float demod = rsqrtf(red[0] + red[1] + red[2] + red[3] + 1e-8f);

    float* dst = g_wmod + ((size_t)(b * CIN + i) * KK) * COUT + o;
#pragma unroll
    for (int t = 0; t < KK; t++)
        dst[t * COUT] = wm[t] * demod;
}

// ---------------------------------------------------------------------------
// Kernel 3: direct conv with packed FFMA2.
// Block: OCT=32 channels x (TH=4 x TW=32) pixels, 256 threads.
// Thread owns 4 oc (as 2 packed pairs) x 4 px.
// ---------------------------------------------------------------------------
__global__ void __launch_bounds__(256, 2) conv_kernel(
    const float* __restrict__ x, float* __restrict__ out) {
    __shared__ __align__(16) float sIn[CIT][TH + 2][ROWW];
    __shared__ __align__(16) float sW[CIT][KK][OCT];

    const int b   = blockIdx.z;
    const int oc0 = blockIdx.y * OCT;
    const int sx  = blockIdx.x & 3;    // WW/TW = 4
    const int sy  = blockIdx.x >> 2;   // HH/TH = 32
    const int y0  = sy * TH;
    const int x0  = sx * TW;

    const int t  = threadIdx.x;
    const int pg = t & 31;             // pixel group (lane)
    const int cg = t >> 5;             // channel group 0..7 (4 oc each)
    const int pr = pg >> 3;            // row 0..3
    const int pc = (pg & 7) << 2;      // col 0,4,...,28

    // acc pairs: accp[p][j] = {oc cg*4+2p, oc cg*4+2p+1} at pixel (pr, pc+j)
    unsigned long long accp[2][4];
#pragma unroll
    for (int p = 0; p < 2; p++)
#pragma unroll
        for (int j = 0; j < 4; j++) accp[p][j] = 0ull;

    const float* xb = x + (size_t)b * CIN * HH * WW;

    for (int ci0 = 0; ci0 < CIN; ci0 += CIT) {
        __syncthreads();
        // ---- stage input tile (CIT x 6 x 34, zero-padded halo) ----
        for (int e = t; e < CIT * (TH + 2) * 34; e += 256) {
            int ci  = e / ((TH + 2) * 34);
            int rem = e % ((TH + 2) * 34);
            int r   = rem / 34;
            int c   = rem % 34;
            int gy  = y0 + r - 1;
            int gx  = x0 + c - 1;
            float v = 0.f;
            if (gy >= 0 && gy < HH && gx >= 0 && gx < WW)
                v = xb[(size_t)(ci0 + ci) * HH * WW + gy * WW + gx];
            sIn[ci][r][c] = v;
        }
        // ---- stage weights (CIT x 9 x 32), coalesced over oc ----
        const float* wb = g_wmod + ((size_t)(b * CIN + ci0) * KK) * COUT + oc0;
        for (int e = t; e < CIT * KK * OCT; e += 256) {
            int ci  = e / (KK * OCT);
            int rem = e % (KK * OCT);
            int tap = rem >> 5;
            int oc  = rem & 31;
            sW[ci][tap][oc] = wb[(size_t)ci * KK * COUT + tap * COUT + oc];
        }
        __syncthreads();

#pragma unroll 1
        for (int ci = 0; ci < CIT; ci++) {
            // x registers: 3 rows x 6 cols (float4 + float2 per row)
            float xin[3][6];
#pragma unroll
            for (int r = 0; r < 3; r++) {
                const float* row = &sIn[ci][pr + r][pc];
                float4 a = *(const float4*)row;
                float2 c = *(const float2*)(row + 4);
                xin[r][0] = a.x; xin[r][1] = a.y; xin[r][2] = a.z; xin[r][3] = a.w;
                xin[r][4] = c.x; xin[r][5] = c.y;
            }
#pragma unroll
            for (int ky = 0; ky < 3; ky++)
#pragma unroll
                for (int kx = 0; kx < 3; kx++) {
                    // weight oc-pairs: one LDS.128 (warp-broadcast, conflict-free)
                    ulonglong2 wp = *(const ulonglong2*)&sW[ci][ky * 3 + kx][cg * 4];
#pragma unroll
                    for (int j = 0; j < 4; j++) {
                        float xv = xin[ky][kx + j];
                        unsigned long long xx = pk2(xv, xv);
                        ffma2(accp[0][j], wp.x, xx);
                        ffma2(accp[1][j], wp.y, xx);
                    }
                }
        }
    }

    // ---- store: unpack oc pairs, float4 along x per oc row ----
#pragma unroll
    for (int p = 0; p < 2; p++) {
        float2 u0 = upk2(accp[p][0]);
        float2 u1 = upk2(accp[p][1]);
        float2 u2 = upk2(accp[p][2]);
        float2 u3 = upk2(accp[p][3]);
        float* ob = out + (((size_t)(b * COUT + oc0 + cg * 4 + 2 * p) * HH) + y0 + pr) * WW + x0 + pc;
        *(float4*)ob = make_float4(u0.x, u1.x, u2.x, u3.x);
        *(float4*)(ob + (size_t)HH * WW) = make_float4(u0.y, u1.y, u2.y, u3.y);
    }
}

// ---------------------------------------------------------------------------
extern "C" void kernel_launch(void* const* d_in, const int* in_sizes, int n_in,
                              void* d_out, int out_size) {
    const float* x      = (const float*)d_in[0];
    const float* style  = (const float*)d_in[1];
    const float* weight = (const float*)d_in[2];
    const float* mod_w  = (const float*)d_in[3];
    const float* mod_b  = (const float*)d_in[4];
    float* out = (float*)d_out;

    modulate_kernel<<<BB * CIN / 8, 256>>>(style, mod_w, mod_b);
    weight_kernel<<<dim3(COUT, BB), CIN>>>(weight);
    conv_kernel<<<dim3((HH / TH) * (WW / TW), COUT / OCT, BB), 256>>>(x, out);
}

// round 6
// speedup vs baseline: 2.6946x; 2.6946x over previous
#include <cuda_runtime.h>
#include <cuda_fp16.h>
#include <cstdint>

#define BB 16
#define CC 128
#define HH 128
#define WW 128
#define SDIM 512
#define PCW 130              // padded width in gmem NHWC layout
#define XROWB 64             // bytes per px per 32-ci chunk (32 * half)
#define PITCH 80             // smem pitch per px/cout row (64B data + 16B pad)

// smem layout (bytes)
#define SB_ROW (PCW * PITCH)         // 10400 per strip row
#define SB_HL  (3 * SB_ROW)          // 31200 per hi/lo strip
#define OFF_SA (2 * SB_HL)           // 62400
#define SA_HL  (128 * PITCH)         // 10240
#define SA_BUF (2 * SA_HL)           // 20480
#define SMEMSZ (OFF_SA + 2 * SA_BUF) // 103360

// device scratch (allocation-free rule)
__device__ __half g_xh[(size_t)BB * 4 * HH * PCW * 32];
__device__ __half g_xl[(size_t)BB * 4 * HH * PCW * 32];
__device__ __half g_wh[(size_t)BB * 4 * 9 * 128 * 32];
__device__ __half g_wl[(size_t)BB * 4 * 9 * 128 * 32];
__device__ float  g_s[BB * CC];

// ---- helpers ----
static __device__ __forceinline__ uint32_t smem_u32(const void* p){
    uint32_t a; asm("{ .reg .u64 t; cvta.to.shared.u64 t, %1; cvt.u32.u64 %0, t; }":"=r"(a):"l"(p)); return a; }
static __device__ __forceinline__ void cp16(uint32_t d, const void* s, uint32_t sz){
    asm volatile("cp.async.cg.shared.global [%0], [%1], 16, %2;"::"r"(d),"l"(s),"r"(sz)); }
static __device__ __forceinline__ void cp_commit(){ asm volatile("cp.async.commit_group;"); }
static __device__ __forceinline__ void cp_wait1(){ asm volatile("cp.async.wait_group 1;":::"memory"); }
static __device__ __forceinline__ void cp_wait0(){ asm volatile("cp.async.wait_group 0;":::"memory"); }
static __device__ __forceinline__ void ldm4(uint32_t* r, uint32_t addr){
    asm volatile("ldmatrix.sync.aligned.m8n8.x4.shared.b16 {%0,%1,%2,%3}, [%4];"
                 : "=r"(r[0]),"=r"(r[1]),"=r"(r[2]),"=r"(r[3]) : "r"(addr)); }
static __device__ __forceinline__ void mma16816(float* c, const uint32_t* a, uint32_t b0, uint32_t b1){
    asm volatile("mma.sync.aligned.m16n8k16.row.col.f32.f16.f16.f32 "
                 "{%0,%1,%2,%3},{%4,%5,%6,%7},{%8,%9},{%0,%1,%2,%3};"
                 : "+f"(c[0]),"+f"(c[1]),"+f"(c[2]),"+f"(c[3])
                 : "r"(a[0]),"r"(a[1]),"r"(a[2]),"r"(a[3]),"r"(b0),"r"(b1)); }

// ---------------- kernel 1: modulation scalars ----------------
__global__ void modulate_kernel(const float* __restrict__ style, const float* __restrict__ mod_w,
                                const float* __restrict__ mod_b){
    const int gw = blockIdx.x*8 + (threadIdx.x>>5), lane = threadIdx.x&31;
    const int b = gw>>7, i = gw&127;
    const float* st = style + b*SDIM;
    const float* mw = mod_w + i*SDIM;
    float acc = 0.f;
#pragma unroll
    for (int d = 0; d < SDIM/32; d++) acc += st[d*32+lane]*mw[d*32+lane];
#pragma unroll
    for (int o = 16; o > 0; o >>= 1) acc += __shfl_xor_sync(~0u, acc, o);
    if (lane==0) g_s[b*CC+i] = acc*0.044194173824159216f + mod_b[i];
}

// ---------------- kernel 2: weights -> fp16 hi/lo, [b][chunk][tap][cout][ci32] ----------------
__global__ void weight_kernel(const float* __restrict__ weight){
    const int o = blockIdx.x, b = blockIdx.y, i = threadIdx.x;
    const float s = g_s[b*CC+i] * 0.029462782549439483f;  // 1/sqrt(1152)
    float wm[9]; float sq = 0.f;
#pragma unroll
    for (int t = 0; t < 9; t++){ float w = weight[(o*CC+i)*9+t]*s; wm[t]=w; sq += w*w; }
    __shared__ float red[4];
#pragma unroll
    for (int off = 16; off > 0; off >>= 1) sq += __shfl_xor_sync(~0u, sq, off);
    if ((i&31)==0) red[i>>5]=sq;
    __syncthreads();
    const float demod = rsqrtf(red[0]+red[1]+red[2]+red[3]+1e-8f);
#pragma unroll
    for (int t = 0; t < 9; t++){
        float w = wm[t]*demod;
        __half h = __float2half_rn(w);
        __half l = __float2half_rn(w - __half2float(h));
        size_t di = (((size_t)((b*4 + (i>>5))*9 + t))*128 + o)*32 + (i&31);
        g_wh[di]=h; g_wl[di]=l;
    }
}

// ---------------- kernel 3: x NCHW fp32 -> padded NHWC fp16 hi/lo ----------------
__global__ void convert_kernel(const float* __restrict__ x){
    __shared__ float tile[64][129];
    const int y = blockIdx.x, b = blockIdx.y, tid = threadIdx.x;
    {   // zero pad columns px=0 and px=129 for all 4 chunks
        int ch = tid>>6, pc = ((tid>>5)&1) ? 129 : 0, ci = tid&31;
        size_t di = (((size_t)((b*4+ch)*HH + y))*PCW + pc)*32 + ci;
        g_xh[di] = __float2half_rn(0.f); g_xl[di] = __float2half_rn(0.f);
    }
#pragma unroll
    for (int half_ = 0; half_ < 2; half_++){
        __syncthreads();
        for (int e = tid; e < 64*128; e += 256){
            int ci = e>>7, c = e&127;
            tile[ci][c] = x[(((size_t)(b*CC + half_*64 + ci))*HH + y)*WW + c];
        }
        __syncthreads();
        for (int e = tid; e < 128*64; e += 256){
            int c = e>>6, cil = e&63;
            float v = tile[cil][c];
            __half h = __float2half_rn(v);
            __half l = __float2half_rn(v - __half2float(h));
            int ch = half_*2 + (cil>>5);
            size_t di = (((size_t)((b*4+ch)*HH + y))*PCW + (c+1))*32 + (cil&31);
            g_xh[di]=h; g_xl[di]=l;
        }
    }
}

// ---------------- kernel 4: conv via mma.sync (HMMA) ----------------
__global__ void __launch_bounds__(256, 2) conv_kernel(float* __restrict__ out){
    extern __shared__ __align__(1024) char sm[];
    const uint32_t sb = smem_u32(sm);
    const int b = blockIdx.y, y = blockIdx.x;
    const int tid = threadIdx.x, wid = tid>>5, lane = tid&31;
    const int m0 = (wid&3)*32, n0 = (wid>>2)*64;
    const int row_off = (lane&7) + ((lane>>3)&1)*8;   // == lane%16
    const int kb16 = ((lane>>4)&1)*16;                // k-half selector (bytes)

    float acc[2][8][4];
#pragma unroll
    for (int mt=0; mt<2; mt++)
#pragma unroll
        for (int nt=0; nt<8; nt++)
#pragma unroll
            for (int j=0; j<4; j++) acc[mt][nt][j] = 0.f;

    const char* gx[2] = {(const char*)g_xh, (const char*)g_xl};
    const char* gw[2] = {(const char*)g_wh, (const char*)g_wl};

#pragma unroll 1
    for (int ch = 0; ch < 4; ch++){
        // ---- stage B strip (3 rows x 130 px, hi+lo) + A tap0 into buf0; one group ----
        for (int e = tid; e < 3120; e += 256){
            int hl = e / 1560, rem = e % 1560;
            int row = rem / 520, q = rem % 520;
            int px = q >> 2, c = q & 3;
            int gy = y - 1 + row;
            uint32_t val = (gy >= 0 && gy < HH) ? 16u : 0u;
            int gyc = gy < 0 ? 0 : (gy > 127 ? 127 : gy);
            const char* src = gx[hl] + ((((size_t)(b*4+ch)*HH + gyc)*PCW + px)*XROWB) + c*16;
            cp16(sb + hl*SB_HL + row*SB_ROW + px*PITCH + c*16, src, val);
        }
        for (int e = tid; e < 1024; e += 256){
            int hl = e >> 9, rem = e & 511;
            int co = rem >> 2, c = rem & 3;
            const char* src = gw[hl] + (((size_t)((b*4+ch)*9 + 0))*4096 + co*32)*2 + c*16;
            cp16(sb + OFF_SA + hl*SA_HL + co*PITCH + c*16, src, 16);
        }
        cp_commit();

#pragma unroll 1
        for (int tap = 0; tap < 9; tap++){
            const int ky = tap / 3, kx = tap % 3;
            const int buf = tap & 1;
            if (tap < 8){
                const int nb = (tap+1) & 1;
                for (int e = tid; e < 1024; e += 256){
                    int hl = e >> 9, rem = e & 511;
                    int co = rem >> 2, c = rem & 3;
                    const char* src = gw[hl] + (((size_t)((b*4+ch)*9 + tap+1))*4096 + co*32)*2 + c*16;
                    cp16(sb + OFF_SA + nb*SA_BUF + hl*SA_HL + co*PITCH + c*16, src, 16);
                }
                cp_commit();
                cp_wait1();
            } else {
                cp_wait0();
            }
            __syncthreads();

#pragma unroll
            for (int ks = 0; ks < 2; ks++){
#pragma unroll
                for (int term = 0; term < 3; term++){
                    const int ahl = (term == 2) ? 1 : 0;
                    const int bhl = (term == 1) ? 1 : 0;
                    uint32_t a[2][4];
#pragma unroll
                    for (int mt = 0; mt < 2; mt++)
                        ldm4(a[mt], sb + OFF_SA + buf*SA_BUF + ahl*SA_HL
                                    + (m0 + mt*16 + row_off)*PITCH + ks*32 + kb16);
                    uint32_t bf[4][4];
#pragma unroll
                    for (int np = 0; np < 4; np++)
                        ldm4(bf[np], sb + bhl*SB_HL + ky*SB_ROW
                                     + (n0 + np*16 + kx + row_off)*PITCH + ks*32 + kb16);
                    // ldmatrix.x4 on B gives {n0-7/kLo, n8-15/kLo, n0-7/kHi, n8-15/kHi};
                    // mma wants (kLo,kHi) of the SAME n-group: pair (r0,r2) and (r1,r3).
#pragma unroll
                    for (int mt = 0; mt < 2; mt++)
#pragma unroll
                        for (int np = 0; np < 4; np++){
                            mma16816(acc[mt][np*2+0], a[mt], bf[np][0], bf[np][2]);
                            mma16816(acc[mt][np*2+1], a[mt], bf[np][1], bf[np][3]);
                        }
                }
            }
            __syncthreads();
        }
    }

    // ---- epilogue: write accumulators ----
#pragma unroll
    for (int mt = 0; mt < 2; mt++)
#pragma unroll
        for (int nt = 0; nt < 8; nt++){
            int m = m0 + mt*16 + (lane>>2);
            int n = n0 + nt*8 + (lane&3)*2;
            float* p = out + (((size_t)(b*CC + m))*HH + y)*WW + n;
            *(float2*)p = make_float2(acc[mt][nt][0], acc[mt][nt][1]);
            *(float2*)(p + (size_t)8*HH*WW) = make_float2(acc[mt][nt][2], acc[mt][nt][3]);
        }
}

// ---------------------------------------------------------------------------
extern "C" void kernel_launch(void* const* d_in, const int* in_sizes, int n_in,
                              void* d_out, int out_size){
    const float* x      = (const float*)d_in[0];
    const float* style  = (const float*)d_in[1];
    const float* weight = (const float*)d_in[2];
    const float* mod_w  = (const float*)d_in[3];
    const float* mod_b  = (const float*)d_in[4];
    float* out = (float*)d_out;

    cudaFuncSetAttribute(conv_kernel, cudaFuncAttributeMaxDynamicSharedMemorySize, SMEMSZ);

    modulate_kernel<<<BB*CC/8, 256>>>(style, mod_w, mod_b);
    weight_kernel<<<dim3(CC, BB), CC>>>(weight);
    convert_kernel<<<dim3(HH, BB), 256>>>(x);
    conv_kernel<<<dim3(HH, BB), 256, SMEMSZ>>>(out);
}